// round 7
// baseline (speedup 1.0000x reference)
#include <cuda_runtime.h>
#include <cstdint>

#define N_NODES 50000
#define EMAX 1600000
#define LDA 144
#define GBLK 782         // ceil(N_NODES/64)
#define SB 512
#define NB 98            // ceil(N_NODES/512)

typedef unsigned long long u64;

// ---------------- scratch (static __device__, no allocation) ----------------
__device__ float g_A[N_NODES * LDA];      // layer-1 GEMM input, stride 144 (cols 134..143 stay 0)
__device__ float g_h1[N_NODES * 128];     // relu output layer 1
__device__ float g_uv[N_NODES * 128];     // cols 0..63 = h1@W2_nbr, cols 64..127 = h1@W2_root
__device__ float g_h2[N_NODES * 64];      // final embeddings
__device__ float g_deginv[N_NODES];
__device__ int   g_deg[N_NODES];
__device__ int   g_cur[N_NODES];
__device__ int   g_rowptr[N_NODES + 1];
__device__ int   g_bsum[NB];
__device__ int   g_boff[NB];
__device__ int   g_csr[EMAX];             // src ids bucketed by dst
__device__ float g_W1[144 * 128];
__device__ float g_W2[128 * 128];

// ---------------- f32x2 helpers ----------------
__device__ __forceinline__ u64 pk(float lo, float hi) {
    u64 r; asm("mov.b64 %0, {%1,%2};" : "=l"(r) : "f"(lo), "f"(hi)); return r;
}
__device__ __forceinline__ float2 upk(u64 v) {
    float2 r; asm("mov.b64 {%0,%1}, %2;" : "=f"(r.x), "=f"(r.y) : "l"(v)); return r;
}
__device__ __forceinline__ void ffma2(u64 &d, u64 a, u64 b) {
    asm("fma.rn.f32x2 %0, %1, %2, %0;" : "+l"(d) : "l"(a), "l"(b));
}

// ---------------- small kernels ----------------
__global__ void k_zero() {
    int t0 = blockIdx.x * blockDim.x + threadIdx.x;
    int stride = gridDim.x * blockDim.x;
    for (int i = t0; i < N_NODES; i += stride) { g_deg[i] = 0; g_cur[i] = 0; }
}

__global__ void k_prepw(const float* __restrict__ W1r, const float* __restrict__ W1n,
                        const float* __restrict__ W2r, const float* __restrict__ W2n) {
    int t0 = blockIdx.x * blockDim.x + threadIdx.x;
    int stride = gridDim.x * blockDim.x;
    for (int i = t0; i < 144 * 128; i += stride) {
        int r = i >> 7, c = i & 127;
        float v = 0.0f;
        if (r < 66) v = W1r[r * 128 + c];
        else if (r >= 68 && r < 134) v = W1n[(r - 68) * 128 + c];
        g_W1[i] = v;
    }
    for (int i = t0; i < 128 * 128; i += stride) {
        int r = i >> 7, c = i & 127;
        g_W2[i] = (c < 64) ? W2n[r * 64 + c] : W2r[r * 64 + (c - 64)];
    }
}

__global__ void k_deg(const int* __restrict__ dst, int E) {
    int i = blockIdx.x * blockDim.x + threadIdx.x;
    if (i < E) atomicAdd(&g_deg[dst[i]], 1);
}

__global__ void k_scan1() {
    __shared__ int s[SB];
    int tid = threadIdx.x;
    int i = blockIdx.x * SB + tid;
    int v = (i < N_NODES) ? g_deg[i] : 0;
    s[tid] = v;
    __syncthreads();
    #pragma unroll
    for (int off = 1; off < SB; off <<= 1) {
        int t = (tid >= off) ? s[tid - off] : 0;
        __syncthreads();
        s[tid] += t;
        __syncthreads();
    }
    if (i < N_NODES) g_rowptr[i] = s[tid] - v;
    if (tid == SB - 1) g_bsum[blockIdx.x] = s[tid];
}

__global__ void k_scan2() {
    if (threadIdx.x == 0 && blockIdx.x == 0) {
        int run = 0;
        for (int b = 0; b < NB; b++) { g_boff[b] = run; run += g_bsum[b]; }
    }
}

__global__ void k_scan3(int E) {
    int i = blockIdx.x * blockDim.x + threadIdx.x;
    if (i < N_NODES) {
        g_rowptr[i] += g_boff[i / SB];
        g_deginv[i] = 1.0f / fmaxf((float)g_deg[i], 1.0f);
    }
    if (i == 0) g_rowptr[N_NODES] = E;
}

__global__ void k_fillcsr(const int* __restrict__ src, const int* __restrict__ dst, int E) {
    int e = blockIdx.x * blockDim.x + threadIdx.x;
    if (e >= E) return;
    int d = dst[e];
    int ofs = atomicAdd(&g_cur[d], 1);
    g_csr[g_rowptr[d] + ofs] = src[e];
}

// A cols 0..67 = concat(x, pos, 0, 0)
__global__ void k_buildA1(const float* __restrict__ x, const float* __restrict__ pos) {
    int i = blockIdx.x * blockDim.x + threadIdx.x;
    if (i >= N_NODES * 68) return;
    int n = i / 68, c = i % 68;
    float v = 0.0f;
    if (c < 64) v = x[n * 64 + c];
    else if (c < 66) v = pos[n * 2 + (c - 64)];
    g_A[(size_t)n * LDA + c] = v;
}

// ---------------- gather-side aggregation, layer 1 ----------------
__global__ __launch_bounds__(256) void k_agg1(const float* __restrict__ x,
                                              const float* __restrict__ pos) {
    int gt = blockIdx.x * blockDim.x + threadIdx.x;
    int w = gt >> 5, lane = gt & 31;
    if (w >= N_NODES) return;
    int start = g_rowptr[w], end = g_rowptr[w + 1];
    float ax = 0.f, ay = 0.f, px = 0.f, py = 0.f;
    const float2* x2 = (const float2*)x;
    const float2* p2 = (const float2*)pos;
    for (int i = start; i < end; i += 32) {
        int m = min(32, end - i);
        int eid = (i + lane < end) ? g_csr[i + lane] : 0;
        for (int j = 0; j < m; j++) {
            int s = __shfl_sync(0xffffffffu, eid, j);
            float2 v = __ldg(x2 + (size_t)s * 32 + lane);
            ax += v.x; ay += v.y;
            if (lane == 0) { float2 p = __ldg(p2 + s); px += p.x; py += p.y; }
        }
    }
    float di = g_deginv[w];
    float* rowp = g_A + (size_t)w * LDA;
    rowp[68 + lane * 2]     = ax * di;
    rowp[68 + lane * 2 + 1] = ay * di;
    if (lane == 0) { rowp[132] = px * di; rowp[133] = py * di; }
}

// ---------------- GEMM with packed f32x2 FMA, duplicate-packed A tile ----------------
// C[M,128] = A[M,K] @ B[K,128]. 64-row blocks, 256 threads,
// thread (ty,tx): rows ty*4..+4, cols tx*8..+8 (contiguous).
// As_dup[kk][2r] = As_dup[kk][2r+1] = A[block_row+r][k0+kk]  -> LDS.128 yields (a,a) pairs
template <int MODE>
__global__ __launch_bounds__(256) void k_gemm(const float* __restrict__ bias) {
    const int K   = (MODE == 0) ? 144 : 128;
    const int lda = (MODE == 0) ? 144 : 128;
    const float* __restrict__ A = (MODE == 0) ? g_A : g_h1;
    const float* __restrict__ B = (MODE == 0) ? g_W1 : g_W2;
    float* __restrict__ C       = (MODE == 0) ? g_h1 : g_uv;

    __shared__ float As[16][132];   // duplicated A tile (128 used); 132*4=528B rows, 16B-aligned
    __shared__ float Bs[16][128];

    int tid = threadIdx.x;
    int block_row = blockIdx.x * 64;
    int arow = tid >> 2, acol4 = tid & 3;           // A tile: 64 rows x 4 float4
    int brow = tid >> 5, bcol4 = tid & 31;          // B tile: 8(+8) rows x 32 float4
    int ty = tid >> 4, tx = tid & 15;
    int a_grow = min(block_row + arow, N_NODES - 1);

    u64 acc[4][4];
    #pragma unroll
    for (int i = 0; i < 4; i++)
        #pragma unroll
        for (int m = 0; m < 4; m++) acc[i][m] = 0ull;

    for (int k0 = 0; k0 < K; k0 += 16) {
        float4 av  = *(const float4*)(A + (size_t)a_grow * lda + k0 + acol4 * 4);
        float4 bv0 = *(const float4*)(B + (size_t)(k0 + brow) * 128 + bcol4 * 4);
        float4 bv1 = *(const float4*)(B + (size_t)(k0 + brow + 8) * 128 + bcol4 * 4);
        __syncthreads();
        ((u64*)&As[acol4 * 4 + 0][0])[arow] = pk(av.x, av.x);
        ((u64*)&As[acol4 * 4 + 1][0])[arow] = pk(av.y, av.y);
        ((u64*)&As[acol4 * 4 + 2][0])[arow] = pk(av.z, av.z);
        ((u64*)&As[acol4 * 4 + 3][0])[arow] = pk(av.w, av.w);
        *(float4*)&Bs[brow][bcol4 * 4] = bv0;
        *(float4*)&Bs[brow + 8][bcol4 * 4] = bv1;
        __syncthreads();
        #pragma unroll
        for (int kk = 0; kk < 16; kk++) {
            ulonglong2 ap0 = *(const ulonglong2*)&As[kk][ty * 8];       // (a0,a0),(a1,a1)
            ulonglong2 ap1 = *(const ulonglong2*)&As[kk][ty * 8 + 4];   // (a2,a2),(a3,a3)
            ulonglong2 bp0 = *(const ulonglong2*)&Bs[kk][tx * 8];       // (b0,b1),(b2,b3)
            ulonglong2 bp1 = *(const ulonglong2*)&Bs[kk][tx * 8 + 4];   // (b4,b5),(b6,b7)
            ffma2(acc[0][0], ap0.x, bp0.x); ffma2(acc[0][1], ap0.x, bp0.y);
            ffma2(acc[0][2], ap0.x, bp1.x); ffma2(acc[0][3], ap0.x, bp1.y);
            ffma2(acc[1][0], ap0.y, bp0.x); ffma2(acc[1][1], ap0.y, bp0.y);
            ffma2(acc[1][2], ap0.y, bp1.x); ffma2(acc[1][3], ap0.y, bp1.y);
            ffma2(acc[2][0], ap1.x, bp0.x); ffma2(acc[2][1], ap1.x, bp0.y);
            ffma2(acc[2][2], ap1.x, bp1.x); ffma2(acc[2][3], ap1.x, bp1.y);
            ffma2(acc[3][0], ap1.y, bp0.x); ffma2(acc[3][1], ap1.y, bp0.y);
            ffma2(acc[3][2], ap1.y, bp1.x); ffma2(acc[3][3], ap1.y, bp1.y);
        }
    }

    float4 bias0, bias1;
    if (MODE == 0) {
        bias0 = ((const float4*)bias)[tx * 2];
        bias1 = ((const float4*)bias)[tx * 2 + 1];
    }
    #pragma unroll
    for (int i = 0; i < 4; i++) {
        int r = block_row + ty * 4 + i;
        if (r >= N_NODES) break;
        float2 c0 = upk(acc[i][0]), c1 = upk(acc[i][1]);
        float2 c2 = upk(acc[i][2]), c3 = upk(acc[i][3]);
        float4 v0 = make_float4(c0.x, c0.y, c1.x, c1.y);
        float4 v1 = make_float4(c2.x, c2.y, c3.x, c3.y);
        if (MODE == 0) {
            v0.x = fmaxf(v0.x + bias0.x, 0.f); v0.y = fmaxf(v0.y + bias0.y, 0.f);
            v0.z = fmaxf(v0.z + bias0.z, 0.f); v0.w = fmaxf(v0.w + bias0.w, 0.f);
            v1.x = fmaxf(v1.x + bias1.x, 0.f); v1.y = fmaxf(v1.y + bias1.y, 0.f);
            v1.z = fmaxf(v1.z + bias1.z, 0.f); v1.w = fmaxf(v1.w + bias1.w, 0.f);
        }
        *(float4*)&C[(size_t)r * 128 + tx * 8]     = v0;
        *(float4*)&C[(size_t)r * 128 + tx * 8 + 4] = v1;
    }
}

// ---------------- gather-side aggregation, layer 2 (+ fused final) ----------------
__global__ __launch_bounds__(256) void k_agg2(const float* __restrict__ b2) {
    int gt = blockIdx.x * blockDim.x + threadIdx.x;
    int w = gt >> 5, lane = gt & 31;
    if (w >= N_NODES) return;
    int start = g_rowptr[w], end = g_rowptr[w + 1];
    float ax = 0.f, ay = 0.f;
    const float2* uv2 = (const float2*)g_uv;
    for (int i = start; i < end; i += 32) {
        int m = min(32, end - i);
        int eid = (i + lane < end) ? g_csr[i + lane] : 0;
        for (int j = 0; j < m; j++) {
            int s = __shfl_sync(0xffffffffu, eid, j);
            float2 v = __ldg(uv2 + (size_t)s * 64 + lane);
            ax += v.x; ay += v.y;
        }
    }
    float di = g_deginv[w];
    float rx = g_uv[(size_t)w * 128 + 64 + lane * 2];
    float ry = g_uv[(size_t)w * 128 + 64 + lane * 2 + 1];
    g_h2[(size_t)w * 64 + lane * 2]     = rx + ax * di + b2[lane * 2];
    g_h2[(size_t)w * 64 + lane * 2 + 1] = ry + ay * di + b2[lane * 2 + 1];
}

// ---------------- edge dot: 4 threads/edge (R1 version) ----------------
__global__ void k_edge(const int* __restrict__ src, const int* __restrict__ dst, int E,
                       float* __restrict__ out) {
    int t = blockIdx.x * blockDim.x + threadIdx.x;
    int e = t >> 2, lane = t & 3;
    if (e >= E) return;
    int s = src[e], d = dst[e];
    const float4* sp = (const float4*)(g_h2 + (size_t)s * 64);
    const float4* dp = (const float4*)(g_h2 + (size_t)d * 64);
    float acc = 0.0f;
    #pragma unroll
    for (int c = 0; c < 4; c++) {
        int ch = lane + 4 * c;
        float4 a = __ldg(&sp[ch]);
        float4 b = __ldg(&dp[ch]);
        acc += a.x * b.x + a.y * b.y + a.z * b.z + a.w * b.w;
    }
    acc += __shfl_xor_sync(0xffffffffu, acc, 1);
    acc += __shfl_xor_sync(0xffffffffu, acc, 2);
    if (lane == 0) out[e] = acc;
}

// ---------------- launch ----------------
extern "C" void kernel_launch(void* const* d_in, const int* in_sizes, int n_in,
                              void* d_out, int out_size) {
    const float* x   = (const float*)d_in[0];
    const float* pos = (const float*)d_in[1];
    const int*   ei  = (const int*)d_in[2];
    const float* W1r = (const float*)d_in[3];
    const float* W1n = (const float*)d_in[4];
    const float* b1  = (const float*)d_in[5];
    const float* W2r = (const float*)d_in[6];
    const float* W2n = (const float*)d_in[7];
    const float* b2  = (const float*)d_in[8];
    float* out = (float*)d_out;

    int E = in_sizes[2] / 2;
    const int* src = ei;
    const int* dst = ei + E;

    k_zero<<<64, 256>>>();
    k_prepw<<<80, 256>>>(W1r, W1n, W2r, W2n);
    k_deg<<<(E + 255) / 256, 256>>>(dst, E);
    k_scan1<<<NB, SB>>>();
    k_scan2<<<1, 32>>>();
    k_scan3<<<(N_NODES + 255) / 256, 256>>>(E);
    k_fillcsr<<<(E + 255) / 256, 256>>>(src, dst, E);
    k_buildA1<<<(N_NODES * 68 + 255) / 256, 256>>>(x, pos);
    k_agg1<<<(N_NODES * 32 + 255) / 256, 256>>>(x, pos);
    k_gemm<0><<<GBLK, 256>>>(b1);
    k_gemm<1><<<GBLK, 256>>>(b1);
    k_agg2<<<(N_NODES * 32 + 255) / 256, 256>>>(b2);
    k_edge<<<(4 * E + 255) / 256, 256>>>(src, dst, E, out);
}

// round 8
// speedup vs baseline: 1.1753x; 1.1753x over previous
#include <cuda_runtime.h>
#include <cstdint>

#define N_NODES 50000
#define EMAX 1600000
#define LDA 144
#define GBLK 782         // ceil(N_NODES/64)
#define SB 512
#define NB 98            // ceil(N_NODES/512)

// ---------------- scratch (static __device__, no allocation) ----------------
__device__ float g_A[N_NODES * LDA];      // layer-1 GEMM input, stride 144 (cols 134..143 stay 0)
__device__ float g_h1[N_NODES * 128];     // relu output layer 1
__device__ float g_uv[N_NODES * 128];     // cols 0..63 = h1@W2_nbr, cols 64..127 = h1@W2_root
__device__ float g_h2[N_NODES * 64];      // final embeddings
__device__ float g_deginv[N_NODES];
__device__ int   g_deg[N_NODES];
__device__ int   g_cur[N_NODES];
__device__ int   g_rowptr[N_NODES + 1];
__device__ int   g_bsum[NB];
__device__ int   g_boff[NB];
__device__ int   g_csr[EMAX];             // src ids bucketed by dst
__device__ int   g_eid[EMAX];             // original edge id bucketed by dst
__device__ float g_W1[144 * 128];
__device__ float g_W2[128 * 128];

// ---------------- small kernels ----------------
__global__ void k_zero() {
    int t0 = blockIdx.x * blockDim.x + threadIdx.x;
    int stride = gridDim.x * blockDim.x;
    for (int i = t0; i < N_NODES; i += stride) { g_deg[i] = 0; g_cur[i] = 0; }
}

__global__ void k_prepw(const float* __restrict__ W1r, const float* __restrict__ W1n,
                        const float* __restrict__ W2r, const float* __restrict__ W2n) {
    int t0 = blockIdx.x * blockDim.x + threadIdx.x;
    int stride = gridDim.x * blockDim.x;
    for (int i = t0; i < 144 * 128; i += stride) {
        int r = i >> 7, c = i & 127;
        float v = 0.0f;
        if (r < 66) v = W1r[r * 128 + c];
        else if (r >= 68 && r < 134) v = W1n[(r - 68) * 128 + c];
        g_W1[i] = v;
    }
    for (int i = t0; i < 128 * 128; i += stride) {
        int r = i >> 7, c = i & 127;
        g_W2[i] = (c < 64) ? W2n[r * 64 + c] : W2r[r * 64 + (c - 64)];
    }
}

__global__ void k_deg(const int* __restrict__ dst, int E) {
    int i = blockIdx.x * blockDim.x + threadIdx.x;
    if (i < E) atomicAdd(&g_deg[dst[i]], 1);
}

__global__ void k_scan1() {
    __shared__ int s[SB];
    int tid = threadIdx.x;
    int i = blockIdx.x * SB + tid;
    int v = (i < N_NODES) ? g_deg[i] : 0;
    s[tid] = v;
    __syncthreads();
    #pragma unroll
    for (int off = 1; off < SB; off <<= 1) {
        int t = (tid >= off) ? s[tid - off] : 0;
        __syncthreads();
        s[tid] += t;
        __syncthreads();
    }
    if (i < N_NODES) g_rowptr[i] = s[tid] - v;
    if (tid == SB - 1) g_bsum[blockIdx.x] = s[tid];
}

__global__ void k_scan2() {
    if (threadIdx.x == 0 && blockIdx.x == 0) {
        int run = 0;
        for (int b = 0; b < NB; b++) { g_boff[b] = run; run += g_bsum[b]; }
    }
}

__global__ void k_scan3(int E) {
    int i = blockIdx.x * blockDim.x + threadIdx.x;
    if (i < N_NODES) {
        g_rowptr[i] += g_boff[i / SB];
        g_deginv[i] = 1.0f / fmaxf((float)g_deg[i], 1.0f);
    }
    if (i == 0) g_rowptr[N_NODES] = E;
}

__global__ void k_fillcsr(const int* __restrict__ src, const int* __restrict__ dst, int E) {
    int e = blockIdx.x * blockDim.x + threadIdx.x;
    if (e >= E) return;
    int d = dst[e];
    int ofs = atomicAdd(&g_cur[d], 1);
    int pos = g_rowptr[d] + ofs;
    g_csr[pos] = src[e];
    g_eid[pos] = e;
}

// A cols 0..67 = concat(x, pos, 0, 0)
__global__ void k_buildA1(const float* __restrict__ x, const float* __restrict__ pos) {
    int i = blockIdx.x * blockDim.x + threadIdx.x;
    if (i >= N_NODES * 68) return;
    int n = i / 68, c = i % 68;
    float v = 0.0f;
    if (c < 64) v = x[n * 64 + c];
    else if (c < 66) v = pos[n * 2 + (c - 64)];
    g_A[(size_t)n * LDA + c] = v;
}

// ---------------- gather-side aggregation, layer 1 ----------------
__global__ __launch_bounds__(256) void k_agg1(const float* __restrict__ x,
                                              const float* __restrict__ pos) {
    int gt = blockIdx.x * blockDim.x + threadIdx.x;
    int w = gt >> 5, lane = gt & 31;
    if (w >= N_NODES) return;
    int start = g_rowptr[w], end = g_rowptr[w + 1];
    float ax = 0.f, ay = 0.f, px = 0.f, py = 0.f;
    const float2* x2 = (const float2*)x;
    const float2* p2 = (const float2*)pos;
    for (int i = start; i < end; i += 32) {
        int m = min(32, end - i);
        int eid = (i + lane < end) ? g_csr[i + lane] : 0;
        for (int j = 0; j < m; j++) {
            int s = __shfl_sync(0xffffffffu, eid, j);
            float2 v = __ldg(x2 + (size_t)s * 32 + lane);
            ax += v.x; ay += v.y;
            if (lane == 0) { float2 p = __ldg(p2 + s); px += p.x; py += p.y; }
        }
    }
    float di = g_deginv[w];
    float* rowp = g_A + (size_t)w * LDA;
    rowp[68 + lane * 2]     = ax * di;
    rowp[68 + lane * 2 + 1] = ay * di;
    if (lane == 0) { rowp[132] = px * di; rowp[133] = py * di; }
}

// ---------------- GEMM (R1 scalar-FFMA version — known good) ----------------
template <int MODE>
__global__ __launch_bounds__(256) void k_gemm(const float* __restrict__ bias) {
    const int K   = (MODE == 0) ? 144 : 128;
    const int lda = (MODE == 0) ? 144 : 128;
    const float* __restrict__ A = (MODE == 0) ? g_A : g_h1;
    const float* __restrict__ B = (MODE == 0) ? g_W1 : g_W2;
    float* __restrict__ C       = (MODE == 0) ? g_h1 : g_uv;

    __shared__ float As[16][65];
    __shared__ float Bs[16][128];

    int tid = threadIdx.x;
    int block_row = blockIdx.x * 64;
    int arow = tid >> 2, acol4 = tid & 3;
    int brow = tid >> 5, bcol4 = tid & 31;
    int ty = tid >> 4, tx = tid & 15;
    int a_grow = min(block_row + arow, N_NODES - 1);

    float acc[4][8];
    #pragma unroll
    for (int i = 0; i < 4; i++)
        #pragma unroll
        for (int j = 0; j < 8; j++) acc[i][j] = 0.0f;

    for (int k0 = 0; k0 < K; k0 += 16) {
        float4 av  = *(const float4*)(A + (size_t)a_grow * lda + k0 + acol4 * 4);
        float4 bv0 = *(const float4*)(B + (size_t)(k0 + brow) * 128 + bcol4 * 4);
        float4 bv1 = *(const float4*)(B + (size_t)(k0 + brow + 8) * 128 + bcol4 * 4);
        __syncthreads();
        As[acol4 * 4 + 0][arow] = av.x;
        As[acol4 * 4 + 1][arow] = av.y;
        As[acol4 * 4 + 2][arow] = av.z;
        As[acol4 * 4 + 3][arow] = av.w;
        *(float4*)&Bs[brow][bcol4 * 4] = bv0;
        *(float4*)&Bs[brow + 8][bcol4 * 4] = bv1;
        __syncthreads();
        #pragma unroll
        for (int kk = 0; kk < 16; kk++) {
            float a[4], b[8];
            #pragma unroll
            for (int i = 0; i < 4; i++) a[i] = As[kk][ty * 4 + i];
            #pragma unroll
            for (int j = 0; j < 8; j++) b[j] = Bs[kk][tx + 16 * j];
            #pragma unroll
            for (int i = 0; i < 4; i++)
                #pragma unroll
                for (int j = 0; j < 8; j++) acc[i][j] += a[i] * b[j];
        }
    }

    #pragma unroll
    for (int i = 0; i < 4; i++) {
        int r = block_row + ty * 4 + i;
        if (r >= N_NODES) break;
        #pragma unroll
        for (int j = 0; j < 8; j++) {
            int c = tx + 16 * j;
            float v = acc[i][j];
            if (MODE == 0) {
                v += bias[c];
                v = fmaxf(v, 0.0f);
            }
            C[(size_t)r * 128 + c] = v;
        }
    }
}

// ---------------- gather-side aggregation, layer 2 (+ fused final) ----------------
__global__ __launch_bounds__(256) void k_agg2(const float* __restrict__ b2) {
    int gt = blockIdx.x * blockDim.x + threadIdx.x;
    int w = gt >> 5, lane = gt & 31;
    if (w >= N_NODES) return;
    int start = g_rowptr[w], end = g_rowptr[w + 1];
    float ax = 0.f, ay = 0.f;
    const float2* uv2 = (const float2*)g_uv;
    for (int i = start; i < end; i += 32) {
        int m = min(32, end - i);
        int eid = (i + lane < end) ? g_csr[i + lane] : 0;
        for (int j = 0; j < m; j++) {
            int s = __shfl_sync(0xffffffffu, eid, j);
            float2 v = __ldg(uv2 + (size_t)s * 64 + lane);
            ax += v.x; ay += v.y;
        }
    }
    float di = g_deginv[w];
    float rx = g_uv[(size_t)w * 128 + 64 + lane * 2];
    float ry = g_uv[(size_t)w * 128 + 64 + lane * 2 + 1];
    g_h2[(size_t)w * 64 + lane * 2]     = rx + ax * di + b2[lane * 2];
    g_h2[(size_t)w * 64 + lane * 2 + 1] = ry + ay * di + b2[lane * 2 + 1];
}

// ---------------- edge dot via CSR: warp per dst, 8 lanes/edge, 4 edges/iter ----
// dst row (256B) held in registers; only src rows gathered -> ~268B L2/edge.
__global__ __launch_bounds__(256) void k_edge3(float* __restrict__ out) {
    int gt = blockIdx.x * blockDim.x + threadIdx.x;
    int w = gt >> 5, lane = gt & 31;
    if (w >= N_NODES) return;
    int g = lane >> 3;          // edge slot within warp (0..3)
    int k = lane & 7;           // feature octet (0..7): floats [k*8, k*8+8)
    const float4* h4 = (const float4*)g_h2;
    float4 d0 = h4[(size_t)w * 16 + k * 2];
    float4 d1 = h4[(size_t)w * 16 + k * 2 + 1];
    int start = g_rowptr[w], end = g_rowptr[w + 1];
    for (int i = start; i < end; i += 4) {
        int idx = i + g;
        bool valid = idx < end;
        int s = 0, eid = 0;
        if (valid) { s = g_csr[idx]; eid = g_eid[idx]; }   // 8 lanes same addr -> broadcast
        float acc = 0.f;
        if (valid) {
            float4 a0 = __ldg(&h4[(size_t)s * 16 + k * 2]);
            float4 a1 = __ldg(&h4[(size_t)s * 16 + k * 2 + 1]);
            acc = a0.x * d0.x + a0.y * d0.y + a0.z * d0.z + a0.w * d0.w
                + a1.x * d1.x + a1.y * d1.y + a1.z * d1.z + a1.w * d1.w;
        }
        acc += __shfl_xor_sync(0xffffffffu, acc, 1);
        acc += __shfl_xor_sync(0xffffffffu, acc, 2);
        acc += __shfl_xor_sync(0xffffffffu, acc, 4);
        if (valid && k == 0) out[eid] = acc;
    }
}

// ---------------- launch ----------------
extern "C" void kernel_launch(void* const* d_in, const int* in_sizes, int n_in,
                              void* d_out, int out_size) {
    const float* x   = (const float*)d_in[0];
    const float* pos = (const float*)d_in[1];
    const int*   ei  = (const int*)d_in[2];
    const float* W1r = (const float*)d_in[3];
    const float* W1n = (const float*)d_in[4];
    const float* b1  = (const float*)d_in[5];
    const float* W2r = (const float*)d_in[6];
    const float* W2n = (const float*)d_in[7];
    const float* b2  = (const float*)d_in[8];
    float* out = (float*)d_out;

    int E = in_sizes[2] / 2;
    const int* src = ei;
    const int* dst = ei + E;

    k_zero<<<64, 256>>>();
    k_prepw<<<80, 256>>>(W1r, W1n, W2r, W2n);
    k_deg<<<(E + 255) / 256, 256>>>(dst, E);
    k_scan1<<<NB, SB>>>();
    k_scan2<<<1, 32>>>();
    k_scan3<<<(N_NODES + 255) / 256, 256>>>(E);
    k_fillcsr<<<(E + 255) / 256, 256>>>(src, dst, E);
    k_buildA1<<<(N_NODES * 68 + 255) / 256, 256>>>(x, pos);
    k_agg1<<<(N_NODES * 32 + 255) / 256, 256>>>(x, pos);
    k_gemm<0><<<GBLK, 256>>>(b1);
    k_gemm<1><<<GBLK, 256>>>(b1);
    k_agg2<<<(N_NODES * 32 + 255) / 256, 256>>>(b2);
    k_edge3<<<(N_NODES * 32 + 255) / 256, 256>>>(out);
}

// round 10
// speedup vs baseline: 1.3096x; 1.1143x over previous
#include <cuda_runtime.h>
#include <cstdint>

#define N_NODES 50000
#define EMAX 1600000
#define LDA 144
#define SB 512
#define NB 98            // ceil(N_NODES/512)
#define GBLK_TC 391      // ceil(N_NODES/128)

// ---------------- scratch (static __device__, no allocation) ----------------
__device__ float g_A[N_NODES * LDA];      // layer-1 GEMM input, stride 144 (cols 134..143 stay 0)
__device__ float g_h1[N_NODES * 128];     // relu output layer 1
__device__ float g_uv[N_NODES * 128];     // cols 0..63 = h1@W2_nbr, cols 64..127 = h1@W2_root
__device__ float g_h2[N_NODES * 64];      // final embeddings
__device__ float g_deginv[N_NODES];
__device__ int   g_deg[N_NODES];
__device__ int   g_cur[N_NODES];
__device__ int   g_rowptr[N_NODES + 1];
__device__ int   g_bsum[NB];
__device__ int   g_boff[NB];
__device__ int   g_csr[EMAX];             // src ids bucketed by dst
__device__ int   g_eid[EMAX];             // original edge id bucketed by dst
__device__ float g_W1hi[144 * 128];
__device__ float g_W1lo[144 * 128];
__device__ float g_W2hi[128 * 128];
__device__ float g_W2lo[128 * 128];

// ---------------- tf32 helpers ----------------
__device__ __forceinline__ uint32_t tf32_of(float f) {
    uint32_t r; asm("cvt.rna.tf32.f32 %0, %1;" : "=r"(r) : "f"(f)); return r;
}
__device__ __forceinline__ void mma_tf32(float* c, const uint32_t* a, uint32_t b0, uint32_t b1) {
    asm volatile(
        "mma.sync.aligned.m16n8k8.row.col.f32.tf32.tf32.f32 "
        "{%0,%1,%2,%3}, {%4,%5,%6,%7}, {%8,%9}, {%0,%1,%2,%3};"
        : "+f"(c[0]), "+f"(c[1]), "+f"(c[2]), "+f"(c[3])
        : "r"(a[0]), "r"(a[1]), "r"(a[2]), "r"(a[3]), "r"(b0), "r"(b1));
}

// ---------------- small kernels ----------------
__global__ void k_zero() {
    int t0 = blockIdx.x * blockDim.x + threadIdx.x;
    int stride = gridDim.x * blockDim.x;
    for (int i = t0; i < N_NODES; i += stride) { g_deg[i] = 0; g_cur[i] = 0; }
}

// W1 combined [144,128] (rows 0-65 W1r, 68-133 W1n, rest 0), W2 combined [128,128]
// (cols 0-63 W2n, 64-127 W2r); each split into tf32 hi + lo.
__global__ void k_prepw(const float* __restrict__ W1r, const float* __restrict__ W1n,
                        const float* __restrict__ W2r, const float* __restrict__ W2n) {
    int t0 = blockIdx.x * blockDim.x + threadIdx.x;
    int stride = gridDim.x * blockDim.x;
    for (int i = t0; i < 144 * 128; i += stride) {
        int r = i >> 7, c = i & 127;
        float v = 0.0f;
        if (r < 66) v = W1r[r * 128 + c];
        else if (r >= 68 && r < 134) v = W1n[(r - 68) * 128 + c];
        float hi = __uint_as_float(tf32_of(v));
        g_W1hi[i] = hi;
        g_W1lo[i] = __uint_as_float(tf32_of(v - hi));
    }
    for (int i = t0; i < 128 * 128; i += stride) {
        int r = i >> 7, c = i & 127;
        float v = (c < 64) ? W2n[r * 64 + c] : W2r[r * 64 + (c - 64)];
        float hi = __uint_as_float(tf32_of(v));
        g_W2hi[i] = hi;
        g_W2lo[i] = __uint_as_float(tf32_of(v - hi));
    }
}

__global__ void k_deg(const int* __restrict__ dst, int E) {
    int i = blockIdx.x * blockDim.x + threadIdx.x;
    if (i < E) atomicAdd(&g_deg[dst[i]], 1);
}

__global__ void k_scan1() {
    __shared__ int s[SB];
    int tid = threadIdx.x;
    int i = blockIdx.x * SB + tid;
    int v = (i < N_NODES) ? g_deg[i] : 0;
    s[tid] = v;
    __syncthreads();
    #pragma unroll
    for (int off = 1; off < SB; off <<= 1) {
        int t = (tid >= off) ? s[tid - off] : 0;
        __syncthreads();
        s[tid] += t;
        __syncthreads();
    }
    if (i < N_NODES) g_rowptr[i] = s[tid] - v;
    if (tid == SB - 1) g_bsum[blockIdx.x] = s[tid];
}

__global__ void k_scan2() {
    if (threadIdx.x == 0 && blockIdx.x == 0) {
        int run = 0;
        for (int b = 0; b < NB; b++) { g_boff[b] = run; run += g_bsum[b]; }
    }
}

__global__ void k_scan3(int E) {
    int i = blockIdx.x * blockDim.x + threadIdx.x;
    if (i < N_NODES) {
        g_rowptr[i] += g_boff[i / SB];
        g_deginv[i] = 1.0f / fmaxf((float)g_deg[i], 1.0f);
    }
    if (i == 0) g_rowptr[N_NODES] = E;
}

__global__ void k_fillcsr(const int* __restrict__ src, const int* __restrict__ dst, int E) {
    int e = blockIdx.x * blockDim.x + threadIdx.x;
    if (e >= E) return;
    int d = dst[e];
    int ofs = atomicAdd(&g_cur[d], 1);
    int pos = g_rowptr[d] + ofs;
    g_csr[pos] = src[e];
    g_eid[pos] = e;
}

// A cols 0..67 = concat(x, pos, 0, 0)
__global__ void k_buildA1(const float* __restrict__ x, const float* __restrict__ pos) {
    int i = blockIdx.x * blockDim.x + threadIdx.x;
    if (i >= N_NODES * 68) return;
    int n = i / 68, c = i % 68;
    float v = 0.0f;
    if (c < 64) v = x[n * 64 + c];
    else if (c < 66) v = pos[n * 2 + (c - 64)];
    g_A[(size_t)n * LDA + c] = v;
}

// ---------------- gather-side aggregation, layer 1 ----------------
__global__ __launch_bounds__(256) void k_agg1(const float* __restrict__ x,
                                              const float* __restrict__ pos) {
    int gt = blockIdx.x * blockDim.x + threadIdx.x;
    int w = gt >> 5, lane = gt & 31;
    if (w >= N_NODES) return;
    int start = g_rowptr[w], end = g_rowptr[w + 1];
    float ax = 0.f, ay = 0.f, px = 0.f, py = 0.f;
    const float2* x2 = (const float2*)x;
    const float2* p2 = (const float2*)pos;
    for (int i = start; i < end; i += 32) {
        int m = min(32, end - i);
        int eid = (i + lane < end) ? g_csr[i + lane] : 0;
        for (int j = 0; j < m; j++) {
            int s = __shfl_sync(0xffffffffu, eid, j);
            float2 v = __ldg(x2 + (size_t)s * 32 + lane);
            ax += v.x; ay += v.y;
            if (lane == 0) { float2 p = __ldg(p2 + s); px += p.x; py += p.y; }
        }
    }
    float di = g_deginv[w];
    float* rowp = g_A + (size_t)w * LDA;
    rowp[68 + lane * 2]     = ax * di;
    rowp[68 + lane * 2 + 1] = ay * di;
    if (lane == 0) { rowp[132] = px * di; rowp[133] = py * di; }
}

// ---------------- tensor-core GEMM: C[M,128] = A[M,K] @ B[K,128] ----------------
// TF32 mma.m16n8k8, 3-term split (Ahi*Bhi + Alo*Bhi + Ahi*Blo).
// 128x128 block tile, 8 warps; warp w: rows w*16..+16, ALL 128 cols (16 n-tiles).
template <int MODE>
__global__ __launch_bounds__(256) void k_gemm_tc(const float* __restrict__ bias) {
    const int K   = (MODE == 0) ? 144 : 128;
    const int lda = (MODE == 0) ? 144 : 128;
    const float* __restrict__ A   = (MODE == 0) ? g_A : g_h1;
    const float* __restrict__ Bhi = (MODE == 0) ? g_W1hi : g_W2hi;
    const float* __restrict__ Blo = (MODE == 0) ? g_W1lo : g_W2lo;
    float* __restrict__ C         = (MODE == 0) ? g_h1 : g_uv;

    __shared__ float As[16][136];   // [k][m]
    __shared__ float Bh[16][136];   // [k][n]
    __shared__ float Bl[16][136];

    int tid  = threadIdx.x;
    int wid  = tid >> 5, lane = tid & 31;
    int tg   = lane & 3, gid = lane >> 2;
    int m0   = blockIdx.x * 128;

    // A loader: 2 threads/row, each 2 float4 (k-halves 0-7 / 8-15)
    int arow = tid >> 1;
    int ak   = (tid & 1) * 8;
    int a_grow = min(m0 + arow, N_NODES - 1);
    // B loader: brow = tid>>4 (0..15), bc=(tid&15)*8
    int brow = tid >> 4;
    int bc   = (tid & 15) * 8;

    float acc[16][4];
    #pragma unroll
    for (int t = 0; t < 16; t++)
        #pragma unroll
        for (int i = 0; i < 4; i++) acc[t][i] = 0.0f;

    for (int k0 = 0; k0 < K; k0 += 16) {
        float4 av0 = *(const float4*)(A + (size_t)a_grow * lda + k0 + ak);
        float4 av1 = *(const float4*)(A + (size_t)a_grow * lda + k0 + ak + 4);
        float4 bh0 = *(const float4*)(Bhi + (size_t)(k0 + brow) * 128 + bc);
        float4 bh1 = *(const float4*)(Bhi + (size_t)(k0 + brow) * 128 + bc + 4);
        float4 bl0 = *(const float4*)(Blo + (size_t)(k0 + brow) * 128 + bc);
        float4 bl1 = *(const float4*)(Blo + (size_t)(k0 + brow) * 128 + bc + 4);
        __syncthreads();
        As[ak + 0][arow] = av0.x; As[ak + 1][arow] = av0.y;
        As[ak + 2][arow] = av0.z; As[ak + 3][arow] = av0.w;
        As[ak + 4][arow] = av1.x; As[ak + 5][arow] = av1.y;
        As[ak + 6][arow] = av1.z; As[ak + 7][arow] = av1.w;
        *(float4*)&Bh[brow][bc]     = bh0;
        *(float4*)&Bh[brow][bc + 4] = bh1;
        *(float4*)&Bl[brow][bc]     = bl0;
        *(float4*)&Bl[brow][bc + 4] = bl1;
        __syncthreads();
        #pragma unroll
        for (int kc = 0; kc < 16; kc += 8) {
            // A fragment: rows m = wid*16 + gid (+8); cols kc+tg (+4)
            float a0f = As[kc + tg][wid * 16 + gid];
            float a1f = As[kc + tg][wid * 16 + gid + 8];
            float a2f = As[kc + tg + 4][wid * 16 + gid];
            float a3f = As[kc + tg + 4][wid * 16 + gid + 8];
            uint32_t ahi[4], alo[4];
            ahi[0] = tf32_of(a0f); alo[0] = tf32_of(a0f - __uint_as_float(ahi[0]));
            ahi[1] = tf32_of(a1f); alo[1] = tf32_of(a1f - __uint_as_float(ahi[1]));
            ahi[2] = tf32_of(a2f); alo[2] = tf32_of(a2f - __uint_as_float(ahi[2]));
            ahi[3] = tf32_of(a3f); alo[3] = tf32_of(a3f - __uint_as_float(ahi[3]));
            #pragma unroll
            for (int t = 0; t < 16; t++) {
                int n = t * 8 + gid;
                uint32_t bh_0 = __float_as_uint(Bh[kc + tg][n]);
                uint32_t bh_1 = __float_as_uint(Bh[kc + tg + 4][n]);
                uint32_t bl_0 = __float_as_uint(Bl[kc + tg][n]);
                uint32_t bl_1 = __float_as_uint(Bl[kc + tg + 4][n]);
                mma_tf32(acc[t], ahi, bh_0, bh_1);
                mma_tf32(acc[t], alo, bh_0, bh_1);
                mma_tf32(acc[t], ahi, bl_0, bl_1);
            }
        }
    }

    // epilogue: c0,c1 -> (row m0+wid*16+gid, cols t*8+tg*2, +1); c2,c3 -> row +8
    int r0 = m0 + wid * 16 + gid;
    int r1 = r0 + 8;
    #pragma unroll
    for (int t = 0; t < 16; t++) {
        int c = t * 8 + tg * 2;
        float v0 = acc[t][0], v1 = acc[t][1], v2 = acc[t][2], v3 = acc[t][3];
        if (MODE == 0) {
            float bb0 = bias[c], bb1 = bias[c + 1];
            v0 = fmaxf(v0 + bb0, 0.f); v1 = fmaxf(v1 + bb1, 0.f);
            v2 = fmaxf(v2 + bb0, 0.f); v3 = fmaxf(v3 + bb1, 0.f);
        }
        if (r0 < N_NODES) *(float2*)&C[(size_t)r0 * 128 + c] = make_float2(v0, v1);
        if (r1 < N_NODES) *(float2*)&C[(size_t)r1 * 128 + c] = make_float2(v2, v3);
    }
}

// ---------------- gather-side aggregation, layer 2 (+ fused final) ----------------
__global__ __launch_bounds__(256) void k_agg2(const float* __restrict__ b2) {
    int gt = blockIdx.x * blockDim.x + threadIdx.x;
    int w = gt >> 5, lane = gt & 31;
    if (w >= N_NODES) return;
    int start = g_rowptr[w], end = g_rowptr[w + 1];
    float ax = 0.f, ay = 0.f;
    const float2* uv2 = (const float2*)g_uv;
    for (int i = start; i < end; i += 32) {
        int m = min(32, end - i);
        int eid = (i + lane < end) ? g_csr[i + lane] : 0;
        for (int j = 0; j < m; j++) {
            int s = __shfl_sync(0xffffffffu, eid, j);
            float2 v = __ldg(uv2 + (size_t)s * 64 + lane);
            ax += v.x; ay += v.y;
        }
    }
    float di = g_deginv[w];
    float rx = g_uv[(size_t)w * 128 + 64 + lane * 2];
    float ry = g_uv[(size_t)w * 128 + 64 + lane * 2 + 1];
    g_h2[(size_t)w * 64 + lane * 2]     = rx + ax * di + b2[lane * 2];
    g_h2[(size_t)w * 64 + lane * 2 + 1] = ry + ay * di + b2[lane * 2 + 1];
}

// ---------------- edge dot via CSR: warp per dst, 8 lanes/edge, 4 edges/iter ----
__global__ __launch_bounds__(256) void k_edge3(float* __restrict__ out) {
    int gt = blockIdx.x * blockDim.x + threadIdx.x;
    int w = gt >> 5, lane = gt & 31;
    if (w >= N_NODES) return;
    int g = lane >> 3;
    int k = lane & 7;
    const float4* h4 = (const float4*)g_h2;
    float4 d0 = h4[(size_t)w * 16 + k * 2];
    float4 d1 = h4[(size_t)w * 16 + k * 2 + 1];
    int start = g_rowptr[w], end = g_rowptr[w + 1];
    for (int i = start; i < end; i += 4) {
        int idx = i + g;
        bool valid = idx < end;
        int s = 0, eid = 0;
        if (valid) { s = g_csr[idx]; eid = g_eid[idx]; }
        float acc = 0.f;
        if (valid) {
            float4 a0 = __ldg(&h4[(size_t)s * 16 + k * 2]);
            float4 a1 = __ldg(&h4[(size_t)s * 16 + k * 2 + 1]);
            acc = a0.x * d0.x + a0.y * d0.y + a0.z * d0.z + a0.w * d0.w
                + a1.x * d1.x + a1.y * d1.y + a1.z * d1.z + a1.w * d1.w;
        }
        acc += __shfl_xor_sync(0xffffffffu, acc, 1);
        acc += __shfl_xor_sync(0xffffffffu, acc, 2);
        acc += __shfl_xor_sync(0xffffffffu, acc, 4);
        if (valid && k == 0) out[eid] = acc;
    }
}

// ---------------- launch ----------------
extern "C" void kernel_launch(void* const* d_in, const int* in_sizes, int n_in,
                              void* d_out, int out_size) {
    const float* x   = (const float*)d_in[0];
    const float* pos = (const float*)d_in[1];
    const int*   ei  = (const int*)d_in[2];
    const float* W1r = (const float*)d_in[3];
    const float* W1n = (const float*)d_in[4];
    const float* b1  = (const float*)d_in[5];
    const float* W2r = (const float*)d_in[6];
    const float* W2n = (const float*)d_in[7];
    const float* b2  = (const float*)d_in[8];
    float* out = (float*)d_out;

    int E = in_sizes[2] / 2;
    const int* src = ei;
    const int* dst = ei + E;

    k_zero<<<64, 256>>>();
    k_prepw<<<80, 256>>>(W1r, W1n, W2r, W2n);
    k_deg<<<(E + 255) / 256, 256>>>(dst, E);
    k_scan1<<<NB, SB>>>();
    k_scan2<<<1, 32>>>();
    k_scan3<<<(N_NODES + 255) / 256, 256>>>(E);
    k_fillcsr<<<(E + 255) / 256, 256>>>(src, dst, E);
    k_buildA1<<<(N_NODES * 68 + 255) / 256, 256>>>(x, pos);
    k_agg1<<<(N_NODES * 32 + 255) / 256, 256>>>(x, pos);
    k_gemm_tc<0><<<GBLK_TC, 256>>>(b1);
    k_gemm_tc<1><<<GBLK_TC, 256>>>(b1);
    k_agg2<<<(N_NODES * 32 + 255) / 256, 256>>>(b2);
    k_edge3<<<(N_NODES * 32 + 255) / 256, 256>>>(out);
}